// round 8
// baseline (speedup 1.0000x reference)
#include <cuda_runtime.h>
#include <math.h>

#define N_NODES 50000
#define N_EDGES 800000
#define MULC 32
#define RADC 8
#define FCC 64
#define EB 8

#define INV_SQRT_MUL 0.17677669529663687f
#define INV_SQRT_RAD 0.35355339059327373f
#define INV_SQRT_FC  0.125f
#define INV_SQRT_NN  0.25f
#define INV_SQRT_2MUL 0.125f
#define INV_SQRT3_C 0.5773502691896258f
#define MIX_C 0.9238795325112867f
#define MIX_S 0.3826834323650898f

typedef unsigned long long u64;

// ---------------- f32x2 packed-math helpers -----------------------------------
__device__ __forceinline__ u64 pack2(float lo, float hi) {
    u64 d; asm("mov.b64 %0, {%1, %2};" : "=l"(d) : "f"(lo), "f"(hi)); return d;
}
__device__ __forceinline__ float2 unpack2(u64 v) {
    float lo, hi; asm("mov.b64 {%0, %1}, %2;" : "=f"(lo), "=f"(hi) : "l"(v));
    return make_float2(lo, hi);
}
__device__ __forceinline__ u64 fma2(u64 a, u64 b, u64 c) {
    u64 d; asm("fma.rn.f32x2 %0, %1, %2, %3;" : "=l"(d) : "l"(a), "l"(b), "l"(c));
    return d;
}
__device__ __forceinline__ u64 ld2(const float2* p) {
    float2 v = *p;
    u64 d; asm("mov.b64 %0, {%1, %2};" : "=l"(d) : "f"(v.x), "f"(v.y)); return d;
}

// gelu(x) = x * sigmoid(2u),  u = 0.79788456(x + 0.044715 x^3)
__device__ __forceinline__ float gelu_fast(float x) {
    float x2 = x * x;
    float arg = x * (-1.5957691216057308f - 0.07135481627352344f * x2);
    float p = __expf(arg);
    return __fdividef(x, 1.0f + p);
}

// ---------------- scratch ------------------------------------------------------
__device__ __align__(16) float g_f0[N_NODES * MULC];
__device__ __align__(16) float g_f1[N_NODES * 3 * MULC];
__device__ __align__(16) float g_self0[N_NODES * MULC];
__device__ __align__(16) float g_self1[N_NODES * 3 * MULC];
__device__ __align__(16) float g_n0[N_NODES * 2 * MULC];
__device__ __align__(16) float g_n1[N_NODES * 3 * 2 * MULC];
__device__ int g_cnt[N_NODES];
__device__ int g_off[N_NODES];
__device__ int g_perm[N_EDGES];

// ---------------- kernel 1: node pre-transforms (f32x2) + zeroing --------------
#define PRE_BLOCKS 800
#define ZERO_BLOCKS 288
#define NPGROUPS (N_NODES / 4)

__global__ __launch_bounds__(256, 3)
void node_pre_kernel(const float* __restrict__ node_s,
                     const float* __restrict__ node_v,
                     const float* __restrict__ Wf0,
                     const float* __restrict__ Ws0,
                     const float* __restrict__ Wf1,
                     const float* __restrict__ Ws1) {
    if (blockIdx.x >= PRE_BLOCKS) {
        int i = (blockIdx.x - PRE_BLOCKS) * blockDim.x + threadIdx.x;
        int stride = ZERO_BLOCKS * blockDim.x;
        float4* p0 = (float4*)g_n0;
        float4* p1 = (float4*)g_n1;
        const float4 z = make_float4(0.f, 0.f, 0.f, 0.f);
        for (int k = i; k < N_NODES * 16; k += stride) p0[k] = z;
        for (int k = i; k < N_NODES * 48; k += stride) p1[k] = z;
        for (int k = i; k < N_NODES; k += stride) g_cnt[k] = 0;
        return;
    }

    __shared__ float2 sWf0p[512], sWs0p[512], sWf1p[512], sWs1p[512];
    __shared__ float sStage[8][512];

    for (int i = threadIdx.x; i < 512; i += blockDim.x) {
        int kp = i >> 5, v = i & 31;
        sWf0p[i] = make_float2(Wf0[(2 * kp) * 32 + v] * INV_SQRT_MUL,
                               Wf0[(2 * kp + 1) * 32 + v] * INV_SQRT_MUL);
        sWs0p[i] = make_float2(Ws0[(2 * kp) * 32 + v] * (INV_SQRT_MUL * MIX_C),
                               Ws0[(2 * kp + 1) * 32 + v] * (INV_SQRT_MUL * MIX_C));
        sWf1p[i] = make_float2(Wf1[(2 * kp) * 32 + v] * INV_SQRT_MUL,
                               Wf1[(2 * kp + 1) * 32 + v] * INV_SQRT_MUL);
        sWs1p[i] = make_float2(Ws1[(2 * kp) * 32 + v] * (INV_SQRT_MUL * MIX_C),
                               Ws1[(2 * kp + 1) * 32 + v] * (INV_SQRT_MUL * MIX_C));
    }
    __syncthreads();

    const int lane = threadIdx.x & 31;
    const int warp = threadIdx.x >> 5;
    float* stg = sStage[warp];

    for (int g = blockIdx.x * 8 + warp; g < NPGROUPS; g += PRE_BLOCKS * 8) {
        const int nb = g * 4;

        #pragma unroll
        for (int m = 0; m < 4; m++) {
            stg[m * 32 + lane] = node_s[(nb + m) * 32 + lane];
            #pragma unroll
            for (int c = 0; c < 3; c++) {
                int j = c * 32 + lane;
                float val = node_v[(nb + m) * 96 + j];
                int u = j / 3, ii = j - u * 3;
                stg[128 + m * 96 + ii * 32 + u] = val;
            }
        }
        __syncwarp();

        u64 af0[4], as0[4];
        #pragma unroll
        for (int m = 0; m < 4; m++) { af0[m] = pack2(0.f, 0.f); as0[m] = pack2(0.f, 0.f); }
        #pragma unroll 8
        for (int kp = 0; kp < 16; kp++) {
            u64 wf = ld2(sWf0p + kp * 32 + lane);
            u64 ws = ld2(sWs0p + kp * 32 + lane);
            #pragma unroll
            for (int m = 0; m < 4; m++) {
                u64 h2 = ld2((const float2*)(stg + m * 32 + 2 * kp));
                af0[m] = fma2(wf, h2, af0[m]);
                as0[m] = fma2(ws, h2, as0[m]);
            }
        }
        #pragma unroll
        for (int m = 0; m < 4; m++) {
            float2 a = unpack2(af0[m]);
            float2 b = unpack2(as0[m]);
            g_f0[(nb + m) * 32 + lane] = a.x + a.y;
            g_self0[(nb + m) * 32 + lane] = b.x + b.y;
        }

        u64 af1[4][3], as1[4][3];
        #pragma unroll
        for (int m = 0; m < 4; m++)
            #pragma unroll
            for (int i = 0; i < 3; i++) { af1[m][i] = pack2(0.f, 0.f); as1[m][i] = pack2(0.f, 0.f); }
        #pragma unroll 4
        for (int kp = 0; kp < 16; kp++) {
            u64 wf = ld2(sWf1p + kp * 32 + lane);
            u64 ws = ld2(sWs1p + kp * 32 + lane);
            #pragma unroll
            for (int m = 0; m < 4; m++) {
                #pragma unroll
                for (int i = 0; i < 3; i++) {
                    u64 h2 = ld2((const float2*)(stg + 128 + m * 96 + i * 32 + 2 * kp));
                    af1[m][i] = fma2(wf, h2, af1[m][i]);
                    as1[m][i] = fma2(ws, h2, as1[m][i]);
                }
            }
        }
        #pragma unroll
        for (int m = 0; m < 4; m++) {
            #pragma unroll
            for (int i = 0; i < 3; i++) {
                float2 a = unpack2(af1[m][i]);
                float2 b = unpack2(as1[m][i]);
                g_f1[(nb + m) * 96 + i * 32 + lane] = a.x + a.y;
                g_self1[(nb + m) * 96 + i * 32 + lane] = b.x + b.y;
            }
        }
        __syncwarp();
    }
}

// ---------------- sort kernels -------------------------------------------------
__global__ void hist_kernel(const int* __restrict__ edge_dst) {
    int i = blockIdx.x * blockDim.x + threadIdx.x;
    if (i < N_EDGES) atomicAdd(&g_cnt[edge_dst[i]], 1);
}

__global__ void scan_kernel() {
    __shared__ int wsum[32];
    __shared__ int s_carry;
    const int tid = threadIdx.x;
    const int lane = tid & 31, wp = tid >> 5;
    if (tid == 0) s_carry = 0;
    __syncthreads();
    for (int b = 0; b < N_NODES; b += 1024) {
        int i = b + tid;
        int v = (i < N_NODES) ? g_cnt[i] : 0;
        int s = v;
        #pragma unroll
        for (int o = 1; o < 32; o <<= 1) {
            int t = __shfl_up_sync(0xffffffffu, s, o);
            if (lane >= o) s += t;
        }
        if (lane == 31) wsum[wp] = s;
        __syncthreads();
        if (wp == 0) {
            int ws = wsum[lane];
            #pragma unroll
            for (int o = 1; o < 32; o <<= 1) {
                int t = __shfl_up_sync(0xffffffffu, ws, o);
                if (lane >= o) ws += t;
            }
            wsum[lane] = ws;
        }
        __syncthreads();
        int carry = s_carry;
        int excl = carry + (wp > 0 ? wsum[wp - 1] : 0) + s - v;
        if (i < N_NODES) g_off[i] = excl;
        __syncthreads();
        if (tid == 1023) s_carry = excl + v;
        __syncthreads();
    }
}

__global__ void scatter_kernel(const int* __restrict__ edge_dst) {
    int i = blockIdx.x * blockDim.x + threadIdx.x;
    if (i < N_EDGES) {
        int d = edge_dst[i];
        int pos = atomicAdd(&g_off[d], 1);
        g_perm[pos] = i;
    }
}

// ---------------- kernel 2: edge phase (f32x2, sorted, aggregated) -------------
#define EDGE_WARPS 8
#define EDGE_GRID 444
#define NB_TOTAL (N_EDGES / EB)      /* 100000 */
#define NB_HALF (NB_TOTAL / 2)       /* 50000 */

// smem floats: sW0 512 | sW1p 4096 | sWP01 4096 | sWP23 4096 | per-warp (hp 512 + meta 16)
#define PW_FLOATS 528
#define EDGE_SMEM_BYTES ((512 + 4096 + 4096 + 4096 + EDGE_WARPS * PW_FLOATS) * 4)

__global__ __launch_bounds__(EDGE_WARPS * 32, 3)
void edge_kernel(int part,
                 const float* __restrict__ sh0,
                 const float* __restrict__ sh1,
                 const float* __restrict__ edge_scalar,
                 const int* __restrict__ edge_src,
                 const int* __restrict__ edge_dst,
                 const float* __restrict__ mlp_w0,
                 const float* __restrict__ mlp_w1,
                 const float* __restrict__ wp0,
                 const float* __restrict__ wp1,
                 const float* __restrict__ wp2,
                 const float* __restrict__ wp3) {
    extern __shared__ float sm[];
    float*  sW0   = sm;
    float2* sW1p  = (float2*)(sm + 512);
    float2* sWP01 = (float2*)(sm + 4608);
    float2* sWP23 = (float2*)(sm + 8704);
    float*  sPW   = sm + 12800;

    for (int i = threadIdx.x; i < RADC * FCC; i += blockDim.x)
        sW0[i] = mlp_w0[i] * INV_SQRT_RAD;
    for (int i = threadIdx.x; i < 2048; i += blockDim.x) {
        int k = i >> 5, c = i & 31;
        sW1p[i] = make_float2(mlp_w1[k * 64 + c] * INV_SQRT_FC,
                              mlp_w1[k * 64 + 32 + c] * INV_SQRT_FC);
    }
    const float wpsc = INV_SQRT_FC * INV_SQRT_NN;
    for (int i = threadIdx.x; i < FCC * MULC; i += blockDim.x) {
        sWP01[i] = make_float2(wp0[i] * wpsc, wp1[i] * wpsc);
        sWP23[i] = make_float2(wp2[i] * wpsc, wp3[i] * (wpsc * INV_SQRT3_C));
    }
    __syncthreads();

    const int lane = threadIdx.x & 31;
    const int warp = threadIdx.x >> 5;
    float4* hp4 = (float4*)(sPW + warp * PW_FLOATS);        // [k][2] float4
    int*    mpid = (int*)(sPW + warp * PW_FLOATS + 512);    // 8 ints

    int gw = blockIdx.x * EDGE_WARPS + warp;
    const int b_lo = part * NB_HALF;
    const int b_hi = b_lo + NB_HALF;

    for (int b = b_lo + gw; b < b_hi; b += EDGE_GRID * EDGE_WARPS) {
        const int eb = b * EB;

        // ---- stage meta via dst-sorted permutation ------------------------------
        if (lane < 8) mpid[lane] = g_perm[eb + lane];
        __syncwarp();
        int srcv = 0, dstv = 0; float sh0v = 0.f;
        if (lane < 8) {
            int pid = mpid[lane];
            srcv = edge_src[pid];
            dstv = edge_dst[pid];
            sh0v = sh0[pid];
        }
        float sh1v = 0.f;
        if (lane < 24) {
            int e = lane / 3;
            sh1v = sh1[(size_t)mpid[e] * 3 + (lane - e * 3)];
        }
        float esA = edge_scalar[(size_t)mpid[lane >> 3] * 8 + (lane & 7)];
        float esB = edge_scalar[(size_t)mpid[4 + (lane >> 3)] * 8 + (lane & 7)];

        // ---- layer 0: 8 -> 64 ---------------------------------------------------
        u64 aL[4] = {0ull, 0ull, 0ull, 0ull};
        u64 aH[4] = {0ull, 0ull, 0ull, 0ull};
        #pragma unroll
        for (int r = 0; r < 8; r++) {
            float wl = sW0[r * 64 + lane];
            float wh = sW0[r * 64 + 32 + lane];
            u64 wl2 = pack2(wl, wl), wh2 = pack2(wh, wh);
            float t0 = __shfl_sync(0xffffffffu, esA, r);
            float t1 = __shfl_sync(0xffffffffu, esA, 8 + r);
            float t2 = __shfl_sync(0xffffffffu, esA, 16 + r);
            float t3 = __shfl_sync(0xffffffffu, esA, 24 + r);
            float t4 = __shfl_sync(0xffffffffu, esB, r);
            float t5 = __shfl_sync(0xffffffffu, esB, 8 + r);
            float t6 = __shfl_sync(0xffffffffu, esB, 16 + r);
            float t7 = __shfl_sync(0xffffffffu, esB, 24 + r);
            u64 e01 = pack2(t0, t1), e23 = pack2(t2, t3);
            u64 e45 = pack2(t4, t5), e67 = pack2(t6, t7);
            aL[0] = fma2(wl2, e01, aL[0]);  aH[0] = fma2(wh2, e01, aH[0]);
            aL[1] = fma2(wl2, e23, aL[1]);  aH[1] = fma2(wh2, e23, aH[1]);
            aL[2] = fma2(wl2, e45, aL[2]);  aH[2] = fma2(wh2, e45, aH[2]);
            aL[3] = fma2(wl2, e67, aL[3]);  aH[3] = fma2(wh2, e67, aH[3]);
        }
        __syncwarp();
        {
            float2 l0 = unpack2(aL[0]), l1 = unpack2(aL[1]);
            float2 l2 = unpack2(aL[2]), l3 = unpack2(aL[3]);
            hp4[lane * 2]     = make_float4(gelu_fast(l0.x), gelu_fast(l0.y),
                                            gelu_fast(l1.x), gelu_fast(l1.y));
            hp4[lane * 2 + 1] = make_float4(gelu_fast(l2.x), gelu_fast(l2.y),
                                            gelu_fast(l3.x), gelu_fast(l3.y));
            float2 h0 = unpack2(aH[0]), h1 = unpack2(aH[1]);
            float2 h2 = unpack2(aH[2]), h3 = unpack2(aH[3]);
            hp4[(32 + lane) * 2]     = make_float4(gelu_fast(h0.x), gelu_fast(h0.y),
                                                   gelu_fast(h1.x), gelu_fast(h1.y));
            hp4[(32 + lane) * 2 + 1] = make_float4(gelu_fast(h2.x), gelu_fast(h2.y),
                                                   gelu_fast(h3.x), gelu_fast(h3.y));
        }
        __syncwarp();

        // ---- layer 1: 64 -> 64 --------------------------------------------------
        u64 bL[4] = {0ull, 0ull, 0ull, 0ull};
        u64 bH[4] = {0ull, 0ull, 0ull, 0ull};
        #pragma unroll 8
        for (int k = 0; k < 64; k++) {
            float2 w = sW1p[k * 32 + lane];
            u64 wl2 = pack2(w.x, w.x), wh2 = pack2(w.y, w.y);
            float4 A = hp4[k * 2];
            float4 B = hp4[k * 2 + 1];
            u64 h01 = pack2(A.x, A.y), h23 = pack2(A.z, A.w);
            u64 h45 = pack2(B.x, B.y), h67 = pack2(B.z, B.w);
            bL[0] = fma2(wl2, h01, bL[0]);  bH[0] = fma2(wh2, h01, bH[0]);
            bL[1] = fma2(wl2, h23, bL[1]);  bH[1] = fma2(wh2, h23, bH[1]);
            bL[2] = fma2(wl2, h45, bL[2]);  bH[2] = fma2(wh2, h45, bH[2]);
            bL[3] = fma2(wl2, h67, bL[3]);  bH[3] = fma2(wh2, h67, bH[3]);
        }
        __syncwarp();
        {
            float2 l0 = unpack2(bL[0]), l1 = unpack2(bL[1]);
            float2 l2 = unpack2(bL[2]), l3 = unpack2(bL[3]);
            hp4[lane * 2]     = make_float4(gelu_fast(l0.x), gelu_fast(l0.y),
                                            gelu_fast(l1.x), gelu_fast(l1.y));
            hp4[lane * 2 + 1] = make_float4(gelu_fast(l2.x), gelu_fast(l2.y),
                                            gelu_fast(l3.x), gelu_fast(l3.y));
            float2 h0 = unpack2(bH[0]), h1 = unpack2(bH[1]);
            float2 h2 = unpack2(bH[2]), h3 = unpack2(bH[3]);
            hp4[(32 + lane) * 2]     = make_float4(gelu_fast(h0.x), gelu_fast(h0.y),
                                                   gelu_fast(h1.x), gelu_fast(h1.y));
            hp4[(32 + lane) * 2 + 1] = make_float4(gelu_fast(h2.x), gelu_fast(h2.y),
                                                   gelu_fast(h3.x), gelu_fast(h3.y));
        }
        __syncwarp();

        // ---- projections pass A: w0, w1 -----------------------------------------
        float w0f[8], w1f[8], w2f[8], w3f[8];
        {
            u64 c0[4] = {0ull, 0ull, 0ull, 0ull};
            u64 c1[4] = {0ull, 0ull, 0ull, 0ull};
            #pragma unroll 8
            for (int k = 0; k < 64; k++) {
                float2 w = sWP01[k * 32 + lane];
                u64 w0d = pack2(w.x, w.x), w1d = pack2(w.y, w.y);
                float4 A = hp4[k * 2];
                float4 B = hp4[k * 2 + 1];
                u64 h01 = pack2(A.x, A.y), h23 = pack2(A.z, A.w);
                u64 h45 = pack2(B.x, B.y), h67 = pack2(B.z, B.w);
                c0[0] = fma2(w0d, h01, c0[0]);  c0[1] = fma2(w0d, h23, c0[1]);
                c0[2] = fma2(w0d, h45, c0[2]);  c0[3] = fma2(w0d, h67, c0[3]);
                c1[0] = fma2(w1d, h01, c1[0]);  c1[1] = fma2(w1d, h23, c1[1]);
                c1[2] = fma2(w1d, h45, c1[2]);  c1[3] = fma2(w1d, h67, c1[3]);
            }
            #pragma unroll
            for (int p = 0; p < 4; p++) {
                float2 t;
                t = unpack2(c0[p]); w0f[2 * p] = t.x; w0f[2 * p + 1] = t.y;
                t = unpack2(c1[p]); w1f[2 * p] = t.x; w1f[2 * p + 1] = t.y;
            }
        }
        // ---- projections pass B: w2, w3 -----------------------------------------
        {
            u64 c2[4] = {0ull, 0ull, 0ull, 0ull};
            u64 c3[4] = {0ull, 0ull, 0ull, 0ull};
            #pragma unroll 8
            for (int k = 0; k < 64; k++) {
                float2 w = sWP23[k * 32 + lane];
                u64 w2d = pack2(w.x, w.x), w3d = pack2(w.y, w.y);
                float4 A = hp4[k * 2];
                float4 B = hp4[k * 2 + 1];
                u64 h01 = pack2(A.x, A.y), h23 = pack2(A.z, A.w);
                u64 h45 = pack2(B.x, B.y), h67 = pack2(B.z, B.w);
                c2[0] = fma2(w2d, h01, c2[0]);  c2[1] = fma2(w2d, h23, c2[1]);
                c2[2] = fma2(w2d, h45, c2[2]);  c2[3] = fma2(w2d, h67, c2[3]);
                c3[0] = fma2(w3d, h01, c3[0]);  c3[1] = fma2(w3d, h23, c3[1]);
                c3[2] = fma2(w3d, h45, c3[2]);  c3[3] = fma2(w3d, h67, c3[3]);
            }
            #pragma unroll
            for (int p = 0; p < 4; p++) {
                float2 t;
                t = unpack2(c2[p]); w2f[2 * p] = t.x; w2f[2 * p + 1] = t.y;
                t = unpack2(c3[p]); w3f[2 * p] = t.x; w3f[2 * p + 1] = t.y;
            }
        }

        // ---- tensor products + run-aggregated scatter ---------------------------
        float ac0 = 0.f, ac3 = 0.f;
        float a1x = 0.f, a1y = 0.f, a1z = 0.f;
        float a2x = 0.f, a2y = 0.f, a2z = 0.f;
        int cur = __shfl_sync(0xffffffffu, dstv, 0);
        #pragma unroll
        for (int j = 0; j < 8; j++) {
            int dst   = __shfl_sync(0xffffffffu, dstv, j);
            int src   = __shfl_sync(0xffffffffu, srcv, j);
            float s0  = __shfl_sync(0xffffffffu, sh0v, j);
            float shx = __shfl_sync(0xffffffffu, sh1v, 3 * j + 0);
            float shy = __shfl_sync(0xffffffffu, sh1v, 3 * j + 1);
            float shz = __shfl_sync(0xffffffffu, sh1v, 3 * j + 2);

            if (dst != cur) {
                float* n0p = g_n0 + cur * 64;
                float* n1p = g_n1 + cur * 192;
                atomicAdd(n0p + lane,      ac0);
                atomicAdd(n0p + 32 + lane, ac3);
                atomicAdd(n1p + lane,            a1x);
                atomicAdd(n1p + 64 + lane,       a1y);
                atomicAdd(n1p + 128 + lane,      a1z);
                atomicAdd(n1p + 32 + lane,       a2x);
                atomicAdd(n1p + 96 + lane,       a2y);
                atomicAdd(n1p + 160 + lane,      a2z);
                ac0 = ac3 = 0.f;
                a1x = a1y = a1z = 0.f;
                a2x = a2y = a2z = 0.f;
                cur = dst;
            }

            const float* f0p = g_f0 + src * 32;
            const float* f1p = g_f1 + src * 96;
            float e0  = f0p[lane];
            float e1x = f1p[lane];
            float e1y = f1p[32 + lane];
            float e1z = f1p[64 + lane];

            ac0 += w0f[j] * e0 * s0;
            float d = e1x * shx + e1y * shy + e1z * shz;
            ac3 += w3f[j] * d;                     // inv_sqrt3 folded into weights
            float w1e0 = w1f[j] * e0;
            float w2s0 = w2f[j] * s0;
            a1x += w1e0 * shx;  a1y += w1e0 * shy;  a1z += w1e0 * shz;
            a2x += w2s0 * e1x;  a2y += w2s0 * e1y;  a2z += w2s0 * e1z;
        }
        {
            float* n0p = g_n0 + cur * 64;
            float* n1p = g_n1 + cur * 192;
            atomicAdd(n0p + lane,      ac0);
            atomicAdd(n0p + 32 + lane, ac3);
            atomicAdd(n1p + lane,            a1x);
            atomicAdd(n1p + 64 + lane,       a1y);
            atomicAdd(n1p + 128 + lane,      a1z);
            atomicAdd(n1p + 32 + lane,       a2x);
            atomicAdd(n1p + 96 + lane,       a2y);
            atomicAdd(n1p + 160 + lane,      a2z);
        }
    }
}

// ---------------- kernel 3: output transform -----------------------------------
#define OUT_WARPS 8
#define OUT_SMEM_BYTES ((2048 + 2048) * 4 + OUT_WARPS * 1024 * 4)

__global__ __launch_bounds__(OUT_WARPS * 32, 2)
void out_kernel(const float* __restrict__ Wout0,
                const float* __restrict__ Wout1,
                float* __restrict__ out) {
    extern __shared__ float smf[];
    float2* sW0t = (float2*)smf;
    float2* sW1t = (float2*)(smf + 2048);
    float*  sStg = smf + 4096;

    const float osc = MIX_S * INV_SQRT_2MUL;
    for (int i = threadIdx.x; i < 1024; i += blockDim.x) {
        int kp = i >> 5, c = i & 31;
        sW0t[i] = make_float2(Wout0[(2 * kp) * 32 + c] * osc,
                              Wout0[(2 * kp + 1) * 32 + c] * osc);
        sW1t[i] = make_float2(Wout1[(2 * kp) * 32 + c] * osc,
                              Wout1[(2 * kp + 1) * 32 + c] * osc);
    }
    __syncthreads();

    const int lane = threadIdx.x & 31;
    const int warp = threadIdx.x >> 5;
    float* stg = sStg + warp * 1024;

    int gw = blockIdx.x * OUT_WARPS + warp;
    int nw = gridDim.x * OUT_WARPS;
    const int NG = N_NODES / 4;

    for (int g = gw; g < NG; g += nw) {
        const int nb = g * 4;

        #pragma unroll
        for (int m = 0; m < 4; m++) {
            const float* n0s = g_n0 + (nb + m) * 64;
            const float* n1s = g_n1 + (nb + m) * 192;
            float* s = stg + m * 256;
            s[lane]      = n0s[lane];
            s[32 + lane] = n0s[32 + lane];
            #pragma unroll
            for (int i = 0; i < 3; i++) {
                s[64 + i * 64 + lane]      = n1s[i * 64 + lane];
                s[64 + i * 64 + 32 + lane] = n1s[i * 64 + 32 + lane];
            }
        }
        __syncwarp();

        u64 accS[4];
        #pragma unroll
        for (int m = 0; m < 4; m++)
            accS[m] = pack2(g_self0[(nb + m) * 32 + lane], 0.0f);
        #pragma unroll 8
        for (int kp = 0; kp < 32; kp++) {
            u64 w2 = ld2(sW0t + kp * 32 + lane);
            #pragma unroll
            for (int m = 0; m < 4; m++) {
                u64 h2 = ld2((const float2*)(stg + m * 256 + 2 * kp));
                accS[m] = fma2(w2, h2, accS[m]);
            }
        }
        #pragma unroll
        for (int m = 0; m < 4; m++) {
            float2 tt = unpack2(accS[m]);
            out[(nb + m) * 128 + lane] = tt.x + tt.y;
        }

        u64 accV[4][3];
        #pragma unroll
        for (int m = 0; m < 4; m++)
            #pragma unroll
            for (int i = 0; i < 3; i++)
                accV[m][i] = pack2(g_self1[(nb + m) * 96 + i * 32 + lane], 0.0f);
        #pragma unroll 4
        for (int kp = 0; kp < 32; kp++) {
            u64 w2 = ld2(sW1t + kp * 32 + lane);
            #pragma unroll
            for (int m = 0; m < 4; m++) {
                const float* s = stg + m * 256 + 64;
                u64 h0 = ld2((const float2*)(s + 0 * 64 + 2 * kp));
                u64 h1 = ld2((const float2*)(s + 1 * 64 + 2 * kp));
                u64 h2v = ld2((const float2*)(s + 2 * 64 + 2 * kp));
                accV[m][0] = fma2(w2, h0, accV[m][0]);
                accV[m][1] = fma2(w2, h1, accV[m][1]);
                accV[m][2] = fma2(w2, h2v, accV[m][2]);
            }
        }
        #pragma unroll
        for (int m = 0; m < 4; m++) {
            #pragma unroll
            for (int i = 0; i < 3; i++) {
                float2 tt = unpack2(accV[m][i]);
                out[(nb + m) * 128 + 32 + lane * 3 + i] = tt.x + tt.y;
            }
        }
    }
}

// ---------------- launch ---------------------------------------------------------
extern "C" void kernel_launch(void* const* d_in, const int* in_sizes, int n_in,
                              void* d_out, int out_size) {
    const float* node_s      = (const float*)d_in[0];
    const float* node_v      = (const float*)d_in[1];
    const float* sh0         = (const float*)d_in[2];
    const float* sh1         = (const float*)d_in[3];
    const float* edge_scalar = (const float*)d_in[4];
    const int*   edge_src    = (const int*)d_in[5];
    const int*   edge_dst    = (const int*)d_in[6];
    const float* W_feat0     = (const float*)d_in[7];
    const float* W_self0     = (const float*)d_in[8];
    const float* W_feat1     = (const float*)d_in[9];
    const float* W_self1     = (const float*)d_in[10];
    const float* mlp_w0      = (const float*)d_in[11];
    const float* mlp_w1      = (const float*)d_in[12];
    const float* wp0         = (const float*)d_in[13];
    const float* wp1         = (const float*)d_in[14];
    const float* wp2         = (const float*)d_in[15];
    const float* wp3         = (const float*)d_in[16];
    const float* W_out0      = (const float*)d_in[17];
    const float* W_out1      = (const float*)d_in[18];
    float* out = (float*)d_out;

    node_pre_kernel<<<PRE_BLOCKS + ZERO_BLOCKS, 256>>>(node_s, node_v,
                                                       W_feat0, W_self0,
                                                       W_feat1, W_self1);
    hist_kernel<<<(N_EDGES + 255) / 256, 256>>>(edge_dst);
    scan_kernel<<<1, 1024>>>();
    scatter_kernel<<<(N_EDGES + 255) / 256, 256>>>(edge_dst);

    cudaFuncSetAttribute(edge_kernel,
                         cudaFuncAttributeMaxDynamicSharedMemorySize,
                         EDGE_SMEM_BYTES);
    edge_kernel<<<EDGE_GRID, EDGE_WARPS * 32, EDGE_SMEM_BYTES>>>(
        0, sh0, sh1, edge_scalar, edge_src, edge_dst,
        mlp_w0, mlp_w1, wp0, wp1, wp2, wp3);
    edge_kernel<<<EDGE_GRID, EDGE_WARPS * 32, EDGE_SMEM_BYTES>>>(
        1, sh0, sh1, edge_scalar, edge_src, edge_dst,
        mlp_w0, mlp_w1, wp0, wp1, wp2, wp3);

    cudaFuncSetAttribute(out_kernel,
                         cudaFuncAttributeMaxDynamicSharedMemorySize,
                         OUT_SMEM_BYTES);
    out_kernel<<<391, OUT_WARPS * 32, OUT_SMEM_BYTES>>>(W_out0, W_out1, out);
}

// round 9
// speedup vs baseline: 1.1760x; 1.1760x over previous
#include <cuda_runtime.h>
#include <math.h>

#define N_NODES 50000
#define N_EDGES 800000
#define MULC 32
#define RADC 8
#define FCC 64
#define EB 8

#define INV_SQRT_MUL 0.17677669529663687f
#define INV_SQRT_RAD 0.35355339059327373f
#define INV_SQRT_FC  0.125f
#define INV_SQRT_NN  0.25f
#define INV_SQRT_2MUL 0.125f
#define INV_SQRT3_C 0.5773502691896258f
#define MIX_C 0.9238795325112867f
#define MIX_S 0.3826834323650898f

typedef unsigned long long u64;

// ---------------- f32x2 packed-math helpers -----------------------------------
__device__ __forceinline__ u64 pack2(float lo, float hi) {
    u64 d; asm("mov.b64 %0, {%1, %2};" : "=l"(d) : "f"(lo), "f"(hi)); return d;
}
__device__ __forceinline__ float2 unpack2(u64 v) {
    float lo, hi; asm("mov.b64 {%0, %1}, %2;" : "=f"(lo), "=f"(hi) : "l"(v));
    return make_float2(lo, hi);
}
__device__ __forceinline__ u64 fma2(u64 a, u64 b, u64 c) {
    u64 d; asm("fma.rn.f32x2 %0, %1, %2, %3;" : "=l"(d) : "l"(a), "l"(b), "l"(c));
    return d;
}
__device__ __forceinline__ u64 ld2(const float2* p) {
    float2 v = *p;
    u64 d; asm("mov.b64 %0, {%1, %2};" : "=l"(d) : "f"(v.x), "f"(v.y)); return d;
}

// gelu(x) = x * sigmoid(2u),  u = 0.79788456(x + 0.044715 x^3)
__device__ __forceinline__ float gelu_fast(float x) {
    float x2 = x * x;
    float arg = x * (-1.5957691216057308f - 0.07135481627352344f * x2);
    float p = __expf(arg);
    return __fdividef(x, 1.0f + p);
}

// ---------------- scratch ------------------------------------------------------
__device__ __align__(16) float g_f0[N_NODES * MULC];
__device__ __align__(16) float g_f1[N_NODES * 3 * MULC];
__device__ __align__(16) float g_self0[N_NODES * MULC];
__device__ __align__(16) float g_self1[N_NODES * 3 * MULC];
__device__ __align__(16) float g_n0[N_NODES * 2 * MULC];
__device__ __align__(16) float g_n1[N_NODES * 3 * 2 * MULC];

// ---------------- kernel 1: node pre-transforms (f32x2) + zeroing --------------
#define PRE_BLOCKS 800
#define ZERO_BLOCKS 288
#define NPGROUPS (N_NODES / 4)

__global__ __launch_bounds__(256, 3)
void node_pre_kernel(const float* __restrict__ node_s,
                     const float* __restrict__ node_v,
                     const float* __restrict__ Wf0,
                     const float* __restrict__ Ws0,
                     const float* __restrict__ Wf1,
                     const float* __restrict__ Ws1) {
    if (blockIdx.x >= PRE_BLOCKS) {
        int i = (blockIdx.x - PRE_BLOCKS) * blockDim.x + threadIdx.x;
        int stride = ZERO_BLOCKS * blockDim.x;
        float4* p0 = (float4*)g_n0;
        float4* p1 = (float4*)g_n1;
        const float4 z = make_float4(0.f, 0.f, 0.f, 0.f);
        for (int k = i; k < N_NODES * 16; k += stride) p0[k] = z;
        for (int k = i; k < N_NODES * 48; k += stride) p1[k] = z;
        return;
    }

    __shared__ float2 sWf0p[512], sWs0p[512], sWf1p[512], sWs1p[512];
    __shared__ float sStage[8][512];

    for (int i = threadIdx.x; i < 512; i += blockDim.x) {
        int kp = i >> 5, v = i & 31;
        sWf0p[i] = make_float2(Wf0[(2 * kp) * 32 + v] * INV_SQRT_MUL,
                               Wf0[(2 * kp + 1) * 32 + v] * INV_SQRT_MUL);
        sWs0p[i] = make_float2(Ws0[(2 * kp) * 32 + v] * (INV_SQRT_MUL * MIX_C),
                               Ws0[(2 * kp + 1) * 32 + v] * (INV_SQRT_MUL * MIX_C));
        sWf1p[i] = make_float2(Wf1[(2 * kp) * 32 + v] * INV_SQRT_MUL,
                               Wf1[(2 * kp + 1) * 32 + v] * INV_SQRT_MUL);
        sWs1p[i] = make_float2(Ws1[(2 * kp) * 32 + v] * (INV_SQRT_MUL * MIX_C),
                               Ws1[(2 * kp + 1) * 32 + v] * (INV_SQRT_MUL * MIX_C));
    }
    __syncthreads();

    const int lane = threadIdx.x & 31;
    const int warp = threadIdx.x >> 5;
    float* stg = sStage[warp];

    for (int g = blockIdx.x * 8 + warp; g < NPGROUPS; g += PRE_BLOCKS * 8) {
        const int nb = g * 4;

        #pragma unroll
        for (int m = 0; m < 4; m++) {
            stg[m * 32 + lane] = node_s[(nb + m) * 32 + lane];
            #pragma unroll
            for (int c = 0; c < 3; c++) {
                int j = c * 32 + lane;
                float val = node_v[(nb + m) * 96 + j];
                int u = j / 3, ii = j - u * 3;
                stg[128 + m * 96 + ii * 32 + u] = val;
            }
        }
        __syncwarp();

        u64 af0[4], as0[4];
        #pragma unroll
        for (int m = 0; m < 4; m++) { af0[m] = pack2(0.f, 0.f); as0[m] = pack2(0.f, 0.f); }
        #pragma unroll 8
        for (int kp = 0; kp < 16; kp++) {
            u64 wf = ld2(sWf0p + kp * 32 + lane);
            u64 ws = ld2(sWs0p + kp * 32 + lane);
            #pragma unroll
            for (int m = 0; m < 4; m++) {
                u64 h2 = ld2((const float2*)(stg + m * 32 + 2 * kp));
                af0[m] = fma2(wf, h2, af0[m]);
                as0[m] = fma2(ws, h2, as0[m]);
            }
        }
        #pragma unroll
        for (int m = 0; m < 4; m++) {
            float2 a = unpack2(af0[m]);
            float2 b = unpack2(as0[m]);
            g_f0[(nb + m) * 32 + lane] = a.x + a.y;
            g_self0[(nb + m) * 32 + lane] = b.x + b.y;
        }

        u64 af1[4][3], as1[4][3];
        #pragma unroll
        for (int m = 0; m < 4; m++)
            #pragma unroll
            for (int i = 0; i < 3; i++) { af1[m][i] = pack2(0.f, 0.f); as1[m][i] = pack2(0.f, 0.f); }
        #pragma unroll 4
        for (int kp = 0; kp < 16; kp++) {
            u64 wf = ld2(sWf1p + kp * 32 + lane);
            u64 ws = ld2(sWs1p + kp * 32 + lane);
            #pragma unroll
            for (int m = 0; m < 4; m++) {
                #pragma unroll
                for (int i = 0; i < 3; i++) {
                    u64 h2 = ld2((const float2*)(stg + 128 + m * 96 + i * 32 + 2 * kp));
                    af1[m][i] = fma2(wf, h2, af1[m][i]);
                    as1[m][i] = fma2(ws, h2, as1[m][i]);
                }
            }
        }
        #pragma unroll
        for (int m = 0; m < 4; m++) {
            #pragma unroll
            for (int i = 0; i < 3; i++) {
                float2 a = unpack2(af1[m][i]);
                float2 b = unpack2(as1[m][i]);
                g_f1[(nb + m) * 96 + i * 32 + lane] = a.x + a.y;
                g_self1[(nb + m) * 96 + i * 32 + lane] = b.x + b.y;
            }
        }
        __syncwarp();
    }
}

// ---------------- kernel 2: edge phase (f32x2, float4-packed LDS) --------------
#define EDGE_WARPS 8
#define EDGE_GRID 296
#define NB_TOTAL (N_EDGES / EB)      /* 100000 */

// smem floats: sW0 512 | sW1q 4096 (float4 k-pairs) | sWP4 8192 (float4) | hp 8*512
#define EDGE_SMEM_BYTES ((512 + 4096 + 8192 + 8 * 512) * 4)   /* 67.6 KB */

__global__ __launch_bounds__(EDGE_WARPS * 32, 2)
void edge_kernel(const float* __restrict__ sh0,
                 const float* __restrict__ sh1,
                 const float* __restrict__ edge_scalar,
                 const int* __restrict__ edge_src,
                 const int* __restrict__ edge_dst,
                 const float* __restrict__ mlp_w0,
                 const float* __restrict__ mlp_w1,
                 const float* __restrict__ wp0,
                 const float* __restrict__ wp1,
                 const float* __restrict__ wp2,
                 const float* __restrict__ wp3) {
    extern __shared__ float sm[];
    float*  sW0  = sm;                         // 8*64
    float4* sW1q = (float4*)(sm + 512);        // [k2][c] = (W1[2k2][c],W1[2k2][c+32],W1[2k2+1][c],W1[2k2+1][c+32])
    float4* sWP4 = (float4*)(sm + 512 + 4096); // [k][c] = (wp0,wp1,wp2,wp3) scaled
    float*  sH   = sm + 512 + 4096 + 8192;     // per-warp 512 floats (hp4)

    for (int i = threadIdx.x; i < RADC * FCC; i += blockDim.x)
        sW0[i] = mlp_w0[i] * INV_SQRT_RAD;
    for (int i = threadIdx.x; i < 1024; i += blockDim.x) {
        int k2 = i >> 5, c = i & 31;
        sW1q[i] = make_float4(mlp_w1[(2 * k2) * 64 + c] * INV_SQRT_FC,
                              mlp_w1[(2 * k2) * 64 + 32 + c] * INV_SQRT_FC,
                              mlp_w1[(2 * k2 + 1) * 64 + c] * INV_SQRT_FC,
                              mlp_w1[(2 * k2 + 1) * 64 + 32 + c] * INV_SQRT_FC);
    }
    const float wpsc = INV_SQRT_FC * INV_SQRT_NN;
    for (int i = threadIdx.x; i < FCC * MULC; i += blockDim.x) {
        sWP4[i] = make_float4(wp0[i] * wpsc, wp1[i] * wpsc,
                              wp2[i] * wpsc, wp3[i] * (wpsc * INV_SQRT3_C));
    }
    __syncthreads();

    const int lane = threadIdx.x & 31;
    const int warp = threadIdx.x >> 5;
    float4* hp4 = (float4*)(sH + warp * 512);   // [k][2] float4: edges 0-3 | 4-7

    int gw = blockIdx.x * EDGE_WARPS + warp;
    const int nw = EDGE_GRID * EDGE_WARPS;

    for (int b = gw; b < NB_TOTAL; b += nw) {
        const int eb = b * EB;

        float esA = edge_scalar[eb * 8 + lane];
        float esB = edge_scalar[eb * 8 + 32 + lane];
        int srcv = 0, dstv = 0; float sh0v = 0.f, sh1v = 0.f;
        if (lane < 8) {
            srcv = edge_src[eb + lane];
            dstv = edge_dst[eb + lane];
            sh0v = sh0[eb + lane];
        }
        if (lane < 24) sh1v = sh1[eb * 3 + lane];

        // ---- layer 0: 8 -> 64 ---------------------------------------------------
        u64 aL[4] = {0ull, 0ull, 0ull, 0ull};
        u64 aH[4] = {0ull, 0ull, 0ull, 0ull};
        #pragma unroll
        for (int r = 0; r < 8; r++) {
            float wl = sW0[r * 64 + lane];
            float wh = sW0[r * 64 + 32 + lane];
            u64 wl2 = pack2(wl, wl), wh2 = pack2(wh, wh);
            float t0 = __shfl_sync(0xffffffffu, esA, r);
            float t1 = __shfl_sync(0xffffffffu, esA, 8 + r);
            float t2 = __shfl_sync(0xffffffffu, esA, 16 + r);
            float t3 = __shfl_sync(0xffffffffu, esA, 24 + r);
            float t4 = __shfl_sync(0xffffffffu, esB, r);
            float t5 = __shfl_sync(0xffffffffu, esB, 8 + r);
            float t6 = __shfl_sync(0xffffffffu, esB, 16 + r);
            float t7 = __shfl_sync(0xffffffffu, esB, 24 + r);
            u64 e01 = pack2(t0, t1), e23 = pack2(t2, t3);
            u64 e45 = pack2(t4, t5), e67 = pack2(t6, t7);
            aL[0] = fma2(wl2, e01, aL[0]);  aH[0] = fma2(wh2, e01, aH[0]);
            aL[1] = fma2(wl2, e23, aL[1]);  aH[1] = fma2(wh2, e23, aH[1]);
            aL[2] = fma2(wl2, e45, aL[2]);  aH[2] = fma2(wh2, e45, aH[2]);
            aL[3] = fma2(wl2, e67, aL[3]);  aH[3] = fma2(wh2, e67, aH[3]);
        }
        __syncwarp();
        {
            float2 l0 = unpack2(aL[0]), l1 = unpack2(aL[1]);
            float2 l2 = unpack2(aL[2]), l3 = unpack2(aL[3]);
            hp4[lane * 2]     = make_float4(gelu_fast(l0.x), gelu_fast(l0.y),
                                            gelu_fast(l1.x), gelu_fast(l1.y));
            hp4[lane * 2 + 1] = make_float4(gelu_fast(l2.x), gelu_fast(l2.y),
                                            gelu_fast(l3.x), gelu_fast(l3.y));
            float2 h0 = unpack2(aH[0]), h1 = unpack2(aH[1]);
            float2 h2 = unpack2(aH[2]), h3 = unpack2(aH[3]);
            hp4[(32 + lane) * 2]     = make_float4(gelu_fast(h0.x), gelu_fast(h0.y),
                                                   gelu_fast(h1.x), gelu_fast(h1.y));
            hp4[(32 + lane) * 2 + 1] = make_float4(gelu_fast(h2.x), gelu_fast(h2.y),
                                                   gelu_fast(h3.x), gelu_fast(h3.y));
        }
        __syncwarp();

        // ---- layer 1: 64 -> 64 (k-pair float4 weights) ---------------------------
        u64 bL[4] = {0ull, 0ull, 0ull, 0ull};
        u64 bH[4] = {0ull, 0ull, 0ull, 0ull};
        #pragma unroll 8
        for (int k2 = 0; k2 < 32; k2++) {
            float4 w4 = sW1q[k2 * 32 + lane];
            float4 A0 = hp4[(2 * k2) * 2];
            float4 B0 = hp4[(2 * k2) * 2 + 1];
            float4 A1 = hp4[(2 * k2 + 1) * 2];
            float4 B1 = hp4[(2 * k2 + 1) * 2 + 1];
            u64 wl0 = pack2(w4.x, w4.x), wh0 = pack2(w4.y, w4.y);
            u64 h01 = pack2(A0.x, A0.y), h23 = pack2(A0.z, A0.w);
            u64 h45 = pack2(B0.x, B0.y), h67 = pack2(B0.z, B0.w);
            bL[0] = fma2(wl0, h01, bL[0]);  bH[0] = fma2(wh0, h01, bH[0]);
            bL[1] = fma2(wl0, h23, bL[1]);  bH[1] = fma2(wh0, h23, bH[1]);
            bL[2] = fma2(wl0, h45, bL[2]);  bH[2] = fma2(wh0, h45, bH[2]);
            bL[3] = fma2(wl0, h67, bL[3]);  bH[3] = fma2(wh0, h67, bH[3]);
            u64 wl1 = pack2(w4.z, w4.z), wh1 = pack2(w4.w, w4.w);
            u64 g01 = pack2(A1.x, A1.y), g23 = pack2(A1.z, A1.w);
            u64 g45 = pack2(B1.x, B1.y), g67 = pack2(B1.z, B1.w);
            bL[0] = fma2(wl1, g01, bL[0]);  bH[0] = fma2(wh1, g01, bH[0]);
            bL[1] = fma2(wl1, g23, bL[1]);  bH[1] = fma2(wh1, g23, bH[1]);
            bL[2] = fma2(wl1, g45, bL[2]);  bH[2] = fma2(wh1, g45, bH[2]);
            bL[3] = fma2(wl1, g67, bL[3]);  bH[3] = fma2(wh1, g67, bH[3]);
        }
        __syncwarp();
        {
            float2 l0 = unpack2(bL[0]), l1 = unpack2(bL[1]);
            float2 l2 = unpack2(bL[2]), l3 = unpack2(bL[3]);
            hp4[lane * 2]     = make_float4(gelu_fast(l0.x), gelu_fast(l0.y),
                                            gelu_fast(l1.x), gelu_fast(l1.y));
            hp4[lane * 2 + 1] = make_float4(gelu_fast(l2.x), gelu_fast(l2.y),
                                            gelu_fast(l3.x), gelu_fast(l3.y));
            float2 h0 = unpack2(bH[0]), h1 = unpack2(bH[1]);
            float2 h2 = unpack2(bH[2]), h3 = unpack2(bH[3]);
            hp4[(32 + lane) * 2]     = make_float4(gelu_fast(h0.x), gelu_fast(h0.y),
                                                   gelu_fast(h1.x), gelu_fast(h1.y));
            hp4[(32 + lane) * 2 + 1] = make_float4(gelu_fast(h2.x), gelu_fast(h2.y),
                                                   gelu_fast(h3.x), gelu_fast(h3.y));
        }
        __syncwarp();

        // ---- fused projections: 64 -> 4x32 (1 LDS.128 weights + 2 LDS.128 h / k) -
        u64 c0[4] = {0ull, 0ull, 0ull, 0ull};
        u64 c1[4] = {0ull, 0ull, 0ull, 0ull};
        u64 c2[4] = {0ull, 0ull, 0ull, 0ull};
        u64 c3[4] = {0ull, 0ull, 0ull, 0ull};
        #pragma unroll 4
        for (int k = 0; k < 64; k++) {
            float4 w4 = sWP4[k * 32 + lane];
            float4 A = hp4[k * 2];
            float4 B = hp4[k * 2 + 1];
            u64 h01 = pack2(A.x, A.y), h23 = pack2(A.z, A.w);
            u64 h45 = pack2(B.x, B.y), h67 = pack2(B.z, B.w);
            u64 w0d = pack2(w4.x, w4.x), w1d = pack2(w4.y, w4.y);
            u64 w2d = pack2(w4.z, w4.z), w3d = pack2(w4.w, w4.w);
            c0[0] = fma2(w0d, h01, c0[0]);  c0[1] = fma2(w0d, h23, c0[1]);
            c0[2] = fma2(w0d, h45, c0[2]);  c0[3] = fma2(w0d, h67, c0[3]);
            c1[0] = fma2(w1d, h01, c1[0]);  c1[1] = fma2(w1d, h23, c1[1]);
            c1[2] = fma2(w1d, h45, c1[2]);  c1[3] = fma2(w1d, h67, c1[3]);
            c2[0] = fma2(w2d, h01, c2[0]);  c2[1] = fma2(w2d, h23, c2[1]);
            c2[2] = fma2(w2d, h45, c2[2]);  c2[3] = fma2(w2d, h67, c2[3]);
            c3[0] = fma2(w3d, h01, c3[0]);  c3[1] = fma2(w3d, h23, c3[1]);
            c3[2] = fma2(w3d, h45, c3[2]);  c3[3] = fma2(w3d, h67, c3[3]);
        }

        float w0f[8], w1f[8], w2f[8], w3f[8];
        #pragma unroll
        for (int p = 0; p < 4; p++) {
            float2 t;
            t = unpack2(c0[p]); w0f[2 * p] = t.x; w0f[2 * p + 1] = t.y;
            t = unpack2(c1[p]); w1f[2 * p] = t.x; w1f[2 * p + 1] = t.y;
            t = unpack2(c2[p]); w2f[2 * p] = t.x; w2f[2 * p + 1] = t.y;
            t = unpack2(c3[p]); w3f[2 * p] = t.x; w3f[2 * p + 1] = t.y;
        }

        // ---- tensor products + scatter-add ---------------------------------------
        #pragma unroll
        for (int j = 0; j < 8; j++) {
            int src   = __shfl_sync(0xffffffffu, srcv, j);
            int dst   = __shfl_sync(0xffffffffu, dstv, j);
            float s0  = __shfl_sync(0xffffffffu, sh0v, j);
            float shx = __shfl_sync(0xffffffffu, sh1v, 3 * j + 0);
            float shy = __shfl_sync(0xffffffffu, sh1v, 3 * j + 1);
            float shz = __shfl_sync(0xffffffffu, sh1v, 3 * j + 2);

            const float* f0p = g_f0 + src * 32;
            const float* f1p = g_f1 + src * 96;
            float e0  = f0p[lane];
            float e1x = f1p[lane];
            float e1y = f1p[32 + lane];
            float e1z = f1p[64 + lane];

            float p0 = w0f[j] * e0 * s0;
            float d  = e1x * shx + e1y * shy + e1z * shz;
            float p3 = w3f[j] * d;                  // inv_sqrt3 folded into wp3
            float w1e0 = w1f[j] * e0;
            float w2s0 = w2f[j] * s0;

            float* n0p = g_n0 + dst * 64;
            float* n1p = g_n1 + dst * 192;
            atomicAdd(n0p + lane,      p0);
            atomicAdd(n0p + 32 + lane, p3);
            atomicAdd(n1p + 0 * 64 + lane,      w1e0 * shx);
            atomicAdd(n1p + 0 * 64 + 32 + lane, w2s0 * e1x);
            atomicAdd(n1p + 1 * 64 + lane,      w1e0 * shy);
            atomicAdd(n1p + 1 * 64 + 32 + lane, w2s0 * e1y);
            atomicAdd(n1p + 2 * 64 + lane,      w1e0 * shz);
            atomicAdd(n1p + 2 * 64 + 32 + lane, w2s0 * e1z);
        }
    }
}

// ---------------- kernel 3: output transform -----------------------------------
#define OUT_WARPS 8
#define OUT_SMEM_BYTES ((2048 + 2048) * 4 + OUT_WARPS * 1024 * 4)

__global__ __launch_bounds__(OUT_WARPS * 32, 2)
void out_kernel(const float* __restrict__ Wout0,
                const float* __restrict__ Wout1,
                float* __restrict__ out) {
    extern __shared__ float smf[];
    float2* sW0t = (float2*)smf;
    float2* sW1t = (float2*)(smf + 2048);
    float*  sStg = smf + 4096;

    const float osc = MIX_S * INV_SQRT_2MUL;
    for (int i = threadIdx.x; i < 1024; i += blockDim.x) {
        int kp = i >> 5, c = i & 31;
        sW0t[i] = make_float2(Wout0[(2 * kp) * 32 + c] * osc,
                              Wout0[(2 * kp + 1) * 32 + c] * osc);
        sW1t[i] = make_float2(Wout1[(2 * kp) * 32 + c] * osc,
                              Wout1[(2 * kp + 1) * 32 + c] * osc);
    }
    __syncthreads();

    const int lane = threadIdx.x & 31;
    const int warp = threadIdx.x >> 5;
    float* stg = sStg + warp * 1024;

    int gw = blockIdx.x * OUT_WARPS + warp;
    int nw = gridDim.x * OUT_WARPS;
    const int NG = N_NODES / 4;

    for (int g = gw; g < NG; g += nw) {
        const int nb = g * 4;

        #pragma unroll
        for (int m = 0; m < 4; m++) {
            const float* n0s = g_n0 + (nb + m) * 64;
            const float* n1s = g_n1 + (nb + m) * 192;
            float* s = stg + m * 256;
            s[lane]      = n0s[lane];
            s[32 + lane] = n0s[32 + lane];
            #pragma unroll
            for (int i = 0; i < 3; i++) {
                s[64 + i * 64 + lane]      = n1s[i * 64 + lane];
                s[64 + i * 64 + 32 + lane] = n1s[i * 64 + 32 + lane];
            }
        }
        __syncwarp();

        u64 accS[4];
        #pragma unroll
        for (int m = 0; m < 4; m++)
            accS[m] = pack2(g_self0[(nb + m) * 32 + lane], 0.0f);
        #pragma unroll 8
        for (int kp = 0; kp < 32; kp++) {
            u64 w2 = ld2(sW0t + kp * 32 + lane);
            #pragma unroll
            for (int m = 0; m < 4; m++) {
                u64 h2 = ld2((const float2*)(stg + m * 256 + 2 * kp));
                accS[m] = fma2(w2, h2, accS[m]);
            }
        }
        #pragma unroll
        for (int m = 0; m < 4; m++) {
            float2 tt = unpack2(accS[m]);
            out[(nb + m) * 128 + lane] = tt.x + tt.y;
        }

        u64 accV[4][3];
        #pragma unroll
        for (int m = 0; m < 4; m++)
            #pragma unroll
            for (int i = 0; i < 3; i++)
                accV[m][i] = pack2(g_self1[(nb + m) * 96 + i * 32 + lane], 0.0f);
        #pragma unroll 4
        for (int kp = 0; kp < 32; kp++) {
            u64 w2 = ld2(sW1t + kp * 32 + lane);
            #pragma unroll
            for (int m = 0; m < 4; m++) {
                const float* s = stg + m * 256 + 64;
                u64 h0 = ld2((const float2*)(s + 0 * 64 + 2 * kp));
                u64 h1 = ld2((const float2*)(s + 1 * 64 + 2 * kp));
                u64 h2v = ld2((const float2*)(s + 2 * 64 + 2 * kp));
                accV[m][0] = fma2(w2, h0, accV[m][0]);
                accV[m][1] = fma2(w2, h1, accV[m][1]);
                accV[m][2] = fma2(w2, h2v, accV[m][2]);
            }
        }
        #pragma unroll
        for (int m = 0; m < 4; m++) {
            #pragma unroll
            for (int i = 0; i < 3; i++) {
                float2 tt = unpack2(accV[m][i]);
                out[(nb + m) * 128 + 32 + lane * 3 + i] = tt.x + tt.y;
            }
        }
    }
}

// ---------------- launch ---------------------------------------------------------
extern "C" void kernel_launch(void* const* d_in, const int* in_sizes, int n_in,
                              void* d_out, int out_size) {
    const float* node_s      = (const float*)d_in[0];
    const float* node_v      = (const float*)d_in[1];
    const float* sh0         = (const float*)d_in[2];
    const float* sh1         = (const float*)d_in[3];
    const float* edge_scalar = (const float*)d_in[4];
    const int*   edge_src    = (const int*)d_in[5];
    const int*   edge_dst    = (const int*)d_in[6];
    const float* W_feat0     = (const float*)d_in[7];
    const float* W_self0     = (const float*)d_in[8];
    const float* W_feat1     = (const float*)d_in[9];
    const float* W_self1     = (const float*)d_in[10];
    const float* mlp_w0      = (const float*)d_in[11];
    const float* mlp_w1      = (const float*)d_in[12];
    const float* wp0         = (const float*)d_in[13];
    const float* wp1         = (const float*)d_in[14];
    const float* wp2         = (const float*)d_in[15];
    const float* wp3         = (const float*)d_in[16];
    const float* W_out0      = (const float*)d_in[17];
    const float* W_out1      = (const float*)d_in[18];
    float* out = (float*)d_out;

    node_pre_kernel<<<PRE_BLOCKS + ZERO_BLOCKS, 256>>>(node_s, node_v,
                                                       W_feat0, W_self0,
                                                       W_feat1, W_self1);

    cudaFuncSetAttribute(edge_kernel,
                         cudaFuncAttributeMaxDynamicSharedMemorySize,
                         EDGE_SMEM_BYTES);
    edge_kernel<<<EDGE_GRID, EDGE_WARPS * 32, EDGE_SMEM_BYTES>>>(
        sh0, sh1, edge_scalar, edge_src, edge_dst,
        mlp_w0, mlp_w1, wp0, wp1, wp2, wp3);

    cudaFuncSetAttribute(out_kernel,
                         cudaFuncAttributeMaxDynamicSharedMemorySize,
                         OUT_SMEM_BYTES);
    out_kernel<<<391, OUT_WARPS * 32, OUT_SMEM_BYTES>>>(W_out0, W_out1, out);
}